// round 2
// baseline (speedup 1.0000x reference)
#include <cuda_runtime.h>
#include <math.h>

#define BB   64
#define LL   512
#define EE   256
#define PPF  128          // 2*P
#define KK   512
#define HH   512
#define TT   53
#define PROW 516          // padded L (2-halo each side), used for both embed & pos
#define LT   128
#define KT   128

// ---------------- scratch (static device memory; no allocs allowed) ----------------
__device__ __align__(16) float g_EpadT[BB * EE * PROW];   // [b][e][l+2]  ~33.8 MB
__device__ __align__(16) float g_PpadT[BB * PPF * PROW];  // [b][p][l+1]  ~16.9 MB
__device__ __align__(16) float g_WeffT[5 * EE * KK];      // [d][e][k]     2.6 MB
__device__ __align__(16) float g_WpT[3 * PPF * KK];       // [t][p][k]     0.8 MB
__device__ __align__(16) float g_corr0[BB * KK];          // conv-pad fixup at l=0
__device__ __align__(16) float g_corrL[BB * KK];          // conv-pad fixup at l=511
__device__ __align__(16) float g_pooled[BB * KK];
__device__ __align__(16) float g_com[BB * 2048];          // [subj(768) obj(768) sent_h(512)]

// ---------------- halo zeroing ----------------
__global__ void zero_halo_kernel() {
    const int b = blockIdx.x;
    const int t = threadIdx.x;            // 256
    float* Eb = g_EpadT + (size_t)b * EE * PROW + (size_t)t * PROW;
    Eb[0] = 0.f; Eb[1] = 0.f; Eb[514] = 0.f; Eb[515] = 0.f;
    if (t < PPF) {
        float* Pb = g_PpadT + (size_t)b * PPF * PROW + (size_t)t * PROW;
        Pb[0] = 0.f; Pb[513] = 0.f; Pb[514] = 0.f; Pb[515] = 0.f;
    }
}

// ---------------- fold conv_w into 5-tap embed kernel + 3-tap pos kernel (transposed) ----------------
__global__ void wprep_kernel(const float* __restrict__ conv_w) {
    int idx = blockIdx.x * 256 + threadIdx.x;
    if (idx < 5 * EE * KK) {
        int d = idx / (EE * KK);
        int r = idx % (EE * KK);
        int e = r / KK;
        int k = r % KK;
        float s = 0.f;
#pragma unroll
        for (int j = 0; j < 3; ++j) {
            int t = d - j;                 // offset d-2 = (j-1)+(t-1)
            if (t >= 0 && t < 3)
                s += conv_w[((size_t)k * 896 + j * EE + e) * 3 + t];
        }
        g_WeffT[idx] = s;
    } else {
        int i2 = idx - 5 * EE * KK;
        if (i2 < 3 * PPF * KK) {
            int t = i2 / (PPF * KK);
            int r = i2 % (PPF * KK);
            int p = r / KK;
            int k = r % KK;
            g_WpT[i2] = conv_w[((size_t)k * 896 + 3 * EE + p) * 3 + t];
        }
    }
}

// ---------------- gather: embeddings + position features, transposed layouts ----------------
__global__ void gather_kernel(const int* __restrict__ context,
                              const int* __restrict__ sdis,
                              const int* __restrict__ odis,
                              const float* __restrict__ etab,
                              const float* __restrict__ ptab) {
    const int b   = blockIdx.y;
    const int l   = blockIdx.x * 32 + (threadIdx.x & 31);
    const int grp = threadIdx.x >> 5;     // 0..7
    const int row = b * LL + l;
    const int tok = context[row];
    float* Edst = g_EpadT + (size_t)b * EE * PROW;
    const float* esrc = etab + (size_t)tok * EE;
#pragma unroll 8
    for (int i = 0; i < 32; ++i) {
        int e = grp * 32 + i;
        Edst[(size_t)e * PROW + (l + 2)] = esrc[e];
    }
    const int ds = sdis[row], od = odis[row];
    float* Pdst = g_PpadT + (size_t)b * PPF * PROW;
#pragma unroll 8
    for (int i = 0; i < 16; ++i) {
        int p = grp * 16 + i;
        float v = (p < 64) ? ptab[(size_t)ds * 64 + p]
                           : ptab[(size_t)od * 64 + (p - 64)];
        Pdst[(size_t)p * PROW + (l + 1)] = v;
    }
}

// ---------------- conv-pad boundary corrections ----------------
// Reference zeroes the WHOLE input vector at conv pad positions m=-1, m=L.
// The halo formulation instead reads embed[0] (for j=2 block, t=0, affecting
// out l=0) and embed[L-1] (for j=0 block, t=2, affecting out l=511).
// Compute those two spurious dot products per (b,k) so conv can subtract them.
__global__ void corr_kernel(const float* __restrict__ conv_w) {
    const int b = blockIdx.x;
    const int k = threadIdx.x;            // 512
    __shared__ float e0[EE], eL[EE];
    const float* Eb = g_EpadT + (size_t)b * EE * PROW;
    for (int e = threadIdx.x; e < EE; e += 512) {
        e0[e] = Eb[(size_t)e * PROW + 2];         // embed[b,0,e]
        eL[e] = Eb[(size_t)e * PROW + 2 + 511];   // embed[b,511,e]
    }
    __syncthreads();
    float c0 = 0.f, cL = 0.f;
#pragma unroll 4
    for (int e = 0; e < EE; ++e) {
        c0 += e0[e] * conv_w[((size_t)k * 896 + 2 * EE + e) * 3 + 0];
        cL += eL[e] * conv_w[((size_t)k * 896 + e) * 3 + 2];
    }
    g_corr0[(size_t)b * KK + k] = c0;
    g_corrL[(size_t)b * KK + k] = cL;
}

// ---------------- entity span features (mean / left / right) ----------------
__global__ void entity_kernel(const int* __restrict__ sidx,
                              const int* __restrict__ oidx) {
    const int b = blockIdx.x;
    const int e = threadIdx.x;            // 256
    const float* Eb = g_EpadT + (size_t)b * EE * PROW + (size_t)e * PROW;
    for (int ent = 0; ent < 2; ++ent) {
        const int* ix = ent ? oidx : sidx;
        int s  = ix[b * 2 + 0];
        int en = ix[b * 2 + 1];
        int lo = s < 0 ? 0 : s;
        int hi = en > LL - 1 ? LL - 1 : en;
        float sum = 0.f; int cnt = 0;
        for (int l = lo; l <= hi; ++l) { sum += Eb[l + 2]; ++cnt; }
        float mean = sum / (float)cnt;
        int li = s - 1; if (li < 0) li += LL;       // jax negative-index wrap
        float left = Eb[li + 2];
        float right = 0.f;
        if (en + 1 < LL) {
            int ri = en + 1; if (ri < 0) ri = 0;
            right = Eb[ri + 2];
        }
        float* dst = g_com + (size_t)b * 2048 + ent * 768;
        dst[e] = mean; dst[256 + e] = left; dst[512 + e] = right;
    }
}

// ---------------- fused conv (5-tap embed + 3-tap pos) + max-pool ----------------
__device__ __forceinline__ void mma32(const float (*Asm)[132], const float (*Bsm)[132],
                                      float acc[8][8], int tx, int ty) {
#pragma unroll 4
    for (int e = 0; e < 32; ++e) {
        float4 a0 = *(const float4*)&Asm[e][ty * 4];
        float4 a1 = *(const float4*)&Asm[e][64 + ty * 4];
        float4 b0 = *(const float4*)&Bsm[e][tx * 4];
        float4 b1 = *(const float4*)&Bsm[e][64 + tx * 4];
        float av[8] = {a0.x, a0.y, a0.z, a0.w, a1.x, a1.y, a1.z, a1.w};
        float bv[8] = {b0.x, b0.y, b0.z, b0.w, b1.x, b1.y, b1.z, b1.w};
#pragma unroll
        for (int i = 0; i < 8; ++i)
#pragma unroll
            for (int j = 0; j < 8; ++j)
                acc[i][j] += av[i] * bv[j];
    }
}

__global__ void __launch_bounds__(256, 2) conv_max_kernel(const float* __restrict__ conv_b) {
    const int b  = blockIdx.y;
    const int k0 = blockIdx.x * KT;
    const int tid = threadIdx.x;
    const int tx = tid & 15;
    const int ty = tid >> 4;
    __shared__ __align__(16) float Asm[32][132];
    __shared__ __align__(16) float Bsm[32][132];

    const float* Eb = g_EpadT + (size_t)b * EE * PROW;
    const float* Pb = g_PpadT + (size_t)b * PPF * PROW;

    float maxv[8];
#pragma unroll
    for (int j = 0; j < 8; ++j) maxv[j] = -3.4e38f;

    for (int l0 = 0; l0 < LL; l0 += LT) {
        float acc[8][8];
#pragma unroll
        for (int i = 0; i < 8; ++i)
#pragma unroll
            for (int j = 0; j < 8; ++j) acc[i][j] = 0.f;

        // ---- embed part: 5 taps x 8 e-chunks ----
        for (int d = 0; d < 5; ++d) {
            for (int ec = 0; ec < 8; ++ec) {
                __syncthreads();
                {   // A: 32 e-rows x 128 l-cols (scalar, coalesced)
                    const float* src = Eb + (size_t)(ec * 32) * PROW + (l0 + d);
#pragma unroll
                    for (int i = 0; i < 16; ++i) {
                        int idx = tid + i * 256;
                        int e = idx >> 7, r = idx & 127;
                        Asm[e][r] = src[(size_t)e * PROW + r];
                    }
                }
                {   // B: 32 e-rows x 128 k-cols, float4
                    const float* src = g_WeffT + ((size_t)d * EE + ec * 32) * KK + k0;
#pragma unroll
                    for (int i = 0; i < 4; ++i) {
                        int idx4 = tid + i * 256;
                        int e = idx4 >> 5, c = idx4 & 31;
                        *(float4*)&Bsm[e][c * 4] = *(const float4*)&src[(size_t)e * KK + c * 4];
                    }
                }
                __syncthreads();
                mma32(Asm, Bsm, acc, tx, ty);
            }
        }
        // ---- pos part: 3 taps x 4 p-chunks ----
        for (int t = 0; t < 3; ++t) {
            for (int pc = 0; pc < 4; ++pc) {
                __syncthreads();
                {
                    const float* src = Pb + (size_t)(pc * 32) * PROW + (l0 + t);
#pragma unroll
                    for (int i = 0; i < 16; ++i) {
                        int idx = tid + i * 256;
                        int e = idx >> 7, r = idx & 127;
                        Asm[e][r] = src[(size_t)e * PROW + r];
                    }
                }
                {
                    const float* src = g_WpT + ((size_t)t * PPF + pc * 32) * KK + k0;
#pragma unroll
                    for (int i = 0; i < 4; ++i) {
                        int idx4 = tid + i * 256;
                        int e = idx4 >> 5, c = idx4 & 31;
                        *(float4*)&Bsm[e][c * 4] = *(const float4*)&src[(size_t)e * KK + c * 4];
                    }
                }
                __syncthreads();
                mma32(Asm, Bsm, acc, tx, ty);
            }
        }

        // ---- conv-pad boundary fixups ----
        if (l0 == 0 && ty == 0) {
            // local l = 0 lives in acc row 0
#pragma unroll
            for (int j = 0; j < 8; ++j) {
                int kk = (j < 4) ? (tx * 4 + j) : (64 + tx * 4 + (j - 4));
                acc[0][j] -= g_corr0[(size_t)b * KK + k0 + kk];
            }
        }
        if (l0 == 384 && ty == 15) {
            // local l = 127 (global 511) lives in acc row 7
#pragma unroll
            for (int j = 0; j < 8; ++j) {
                int kk = (j < 4) ? (tx * 4 + j) : (64 + tx * 4 + (j - 4));
                acc[7][j] -= g_corrL[(size_t)b * KK + k0 + kk];
            }
        }

#pragma unroll
        for (int i = 0; i < 8; ++i)
#pragma unroll
            for (int j = 0; j < 8; ++j)
                maxv[j] = fmaxf(maxv[j], acc[i][j]);
    }

    // reduce max across the 16 ty rows
    __syncthreads();
    float* red = &Asm[0][0];              // 16*128 floats, fits
#pragma unroll
    for (int j = 0; j < 8; ++j) {
        int kk = (j < 4) ? (tx * 4 + j) : (64 + tx * 4 + (j - 4));
        red[ty * 128 + kk] = maxv[j];
    }
    __syncthreads();
    if (ty == 0) {
#pragma unroll
        for (int j = 0; j < 8; ++j) {
            int kk = (j < 4) ? (tx * 4 + j) : (64 + tx * 4 + (j - 4));
            float m = red[kk];
#pragma unroll
            for (int r = 1; r < 16; ++r) m = fmaxf(m, red[r * 128 + kk]);
            g_pooled[(size_t)b * KK + k0 + kk] = m + conv_b[k0 + kk];
        }
    }
}

// ---------------- sent_h = tanh(pooled @ lin1_w^T + b) ----------------
__global__ void lin1_kernel(const float* __restrict__ w, const float* __restrict__ bias) {
    const int b = blockIdx.x;
    const int h = threadIdx.x;            // 512
    __shared__ float p[KK];
    p[h] = g_pooled[(size_t)b * KK + h];
    __syncthreads();
    const float* wr = w + (size_t)h * KK;
    float s = bias[h];
#pragma unroll 8
    for (int i = 0; i < KK; ++i) s += p[i] * wr[i];
    g_com[(size_t)b * 2048 + 1536 + h] = tanhf(s);
}

// ---------------- scores = com @ lin2_w^T + b ----------------
__global__ void scores_kernel(const float* __restrict__ w, const float* __restrict__ bias,
                              float* __restrict__ out) {
    const int b = blockIdx.x;
    const int t = threadIdx.x;            // 64
    __shared__ float c[2048];
    for (int i = t; i < 2048; i += 64) c[i] = g_com[(size_t)b * 2048 + i];
    __syncthreads();
    if (t < TT) {
        const float* wr = w + (size_t)t * 2048;
        float s = bias[t];
#pragma unroll 8
        for (int i = 0; i < 2048; ++i) s += c[i] * wr[i];
        out[(size_t)b * TT + t] = s;
    }
}

// ---------------- launch ----------------
extern "C" void kernel_launch(void* const* d_in, const int* in_sizes, int n_in,
                              void* d_out, int out_size) {
    const int*   context = (const int*)  d_in[0];
    const int*   sidx    = (const int*)  d_in[1];
    const int*   oidx    = (const int*)  d_in[2];
    const int*   sdis    = (const int*)  d_in[3];
    const int*   odis    = (const int*)  d_in[4];
    const float* etab    = (const float*)d_in[5];
    const float* ptab    = (const float*)d_in[6];
    const float* conv_w  = (const float*)d_in[7];
    const float* conv_b  = (const float*)d_in[8];
    const float* lin1_w  = (const float*)d_in[9];
    const float* lin1_b  = (const float*)d_in[10];
    const float* lin2_w  = (const float*)d_in[11];
    const float* lin2_b  = (const float*)d_in[12];
    float* out = (float*)d_out;

    zero_halo_kernel<<<BB, 256>>>();
    wprep_kernel<<<3328, 256>>>(conv_w);
    gather_kernel<<<dim3(16, BB), 256>>>(context, sdis, odis, etab, ptab);
    corr_kernel<<<BB, 512>>>(conv_w);
    entity_kernel<<<BB, 256>>>(sidx, oidx);
    conv_max_kernel<<<dim3(4, BB), 256>>>(conv_b);
    lin1_kernel<<<BB, 512>>>(lin1_w, lin1_b);
    scores_kernel<<<BB, 64>>>(lin2_w, lin2_b, out);
}

// round 4
// speedup vs baseline: 1.4426x; 1.4426x over previous
#include <cuda_runtime.h>
#include <mma.h>
#include <math.h>
#include <stdint.h>

using namespace nvcuda;

#define BB   64
#define LL   512
#define EE   256
#define PR   128          // pos feature width (2*P)
#define KK   512
#define TT   53
#define SR   516          // padded rows
#define CH   52           // reduction chunks of 32 (40 embed + 12 pos)
#define ALD  36           // smem leading dim for 32-wide chunks (+4 pad)
#define STAGE_FLOATS (2 * 128 * ALD)        // A + B per stage = 9216 floats
#define SMEM_BYTES   (2 * STAGE_FLOATS * 4) // 73728 B (also covers 128x132 C buf)

// ---------------- static device scratch ----------------
__device__ __align__(16) float g_Epad[BB * SR * EE];   // [b][l+2][e], tf32-rounded
__device__ __align__(16) float g_Ppad[BB * SR * PR];   // [b][l+1][p], tf32-rounded
__device__ __align__(16) float g_Weff2[5 * KK * EE];   // [d][k][e], tf32-rounded
__device__ __align__(16) float g_Wp2[3 * KK * PR];     // [t][k][p], tf32-rounded
__device__ __align__(16) float g_C0w[KK * EE];         // conv_w[k][2E+e][0]
__device__ __align__(16) float g_CLw[KK * EE];         // conv_w[k][e][2]
__device__ __align__(16) float g_corr0[BB * KK];
__device__ __align__(16) float g_corrL[BB * KK];
__device__ __align__(16) float g_pooled[BB * KK];
__device__ __align__(16) float g_com[BB * 2048];

// ---------------- helpers ----------------
__device__ __forceinline__ uint32_t smem_u32(const void* p) {
    uint32_t a;
    asm("{ .reg .u64 t; cvta.to.shared.u64 t, %1; cvt.u32.u64 %0, t; }" : "=r"(a) : "l"(p));
    return a;
}
__device__ __forceinline__ float rna_tf32(float x) {
    uint32_t r;
    asm("cvt.rna.tf32.f32 %0, %1;" : "=r"(r) : "f"(x));
    return __uint_as_float(r);
}
__device__ __forceinline__ void cpa16(uint32_t dst, const void* src) {
    asm volatile("cp.async.cg.shared.global [%0], [%1], 16;" :: "r"(dst), "l"(src) : "memory");
}
#define CP_COMMIT() asm volatile("cp.async.commit_group;" ::: "memory")
#define CP_WAIT(n)  asm volatile("cp.async.wait_group %0;" :: "n"(n) : "memory")

// ---------------- halo zeroing ----------------
__global__ void zero_halo_kernel() {
    const int b = blockIdx.x, t = threadIdx.x;     // 256
    float* Eb = g_Epad + (size_t)b * SR * EE;
    Eb[0 * EE + t] = 0.f; Eb[1 * EE + t] = 0.f;
    Eb[514 * EE + t] = 0.f; Eb[515 * EE + t] = 0.f;
    if (t < PR) {
        float* Pb = g_Ppad + (size_t)b * SR * PR;
        Pb[0 * PR + t] = 0.f; Pb[513 * PR + t] = 0.f;
        Pb[514 * PR + t] = 0.f; Pb[515 * PR + t] = 0.f;
    }
}

// ---------------- weight prep: fold + transpose + tf32 round ----------------
__global__ void wprep_kernel(const float* __restrict__ conv_w) {
    int idx = blockIdx.x * 256 + threadIdx.x;
    const int N1 = 5 * KK * EE;
    const int N2 = 3 * KK * PR;
    const int N3 = KK * EE;
    if (idx < N1) {
        int d = idx / (KK * EE), r = idx % (KK * EE);
        int k = r / EE, e = r % EE;
        float s = 0.f;
#pragma unroll
        for (int j = 0; j < 3; ++j) {
            int t = d - j;
            if (t >= 0 && t < 3)
                s += conv_w[((size_t)k * 896 + j * EE + e) * 3 + t];
        }
        g_Weff2[idx] = rna_tf32(s);
    } else if (idx < N1 + N2) {
        int i2 = idx - N1;
        int t = i2 / (KK * PR), r = i2 % (KK * PR);
        int k = r / PR, p = r % PR;
        g_Wp2[i2] = rna_tf32(conv_w[((size_t)k * 896 + 3 * EE + p) * 3 + t]);
    } else if (idx < N1 + N2 + N3) {
        int i3 = idx - N1 - N2;
        int k = i3 / EE, e = i3 % EE;
        g_C0w[i3] = rna_tf32(conv_w[((size_t)k * 896 + 2 * EE + e) * 3 + 0]);
    } else if (idx < N1 + N2 + 2 * N3) {
        int i4 = idx - N1 - N2 - N3;
        int k = i4 / EE, e = i4 % EE;
        g_CLw[i4] = rna_tf32(conv_w[((size_t)k * 896 + e) * 3 + 2]);
    }
}

// ---------------- gather (natural [l][e] layout, tf32-rounded) ----------------
__global__ void gather_kernel(const int* __restrict__ context,
                              const int* __restrict__ sdis,
                              const int* __restrict__ odis,
                              const float* __restrict__ etab,
                              const float* __restrict__ ptab) {
    const int b = blockIdx.y;
    const int grp = threadIdx.x >> 5, lane = threadIdx.x & 31;
    float* Eb = g_Epad + (size_t)b * SR * EE;
    float* Pb = g_Ppad + (size_t)b * SR * PR;
#pragma unroll
    for (int li = 0; li < 4; ++li) {
        int l = blockIdx.x * 32 + grp * 4 + li;
        int row = b * LL + l;
        int tok = context[row];
        const float* es = etab + (size_t)tok * EE;
#pragma unroll
        for (int it = 0; it < 8; ++it) {
            int e = it * 32 + lane;
            Eb[(size_t)(l + 2) * EE + e] = rna_tf32(es[e]);
        }
        int ds = sdis[row], od = odis[row];
#pragma unroll
        for (int it = 0; it < 4; ++it) {
            int p = it * 32 + lane;
            float v = (p < 64) ? ptab[(size_t)ds * 64 + p]
                               : ptab[(size_t)od * 64 + (p - 64)];
            Pb[(size_t)(l + 1) * PR + p] = rna_tf32(v);
        }
    }
}

// ---------------- boundary corrections (coalesced) ----------------
__global__ void corr_kernel(const int*) {
    const int b = blockIdx.x, tid = threadIdx.x;
    const int wid = tid >> 5, lane = tid & 31;
    __shared__ float e0[EE], eL[EE];
    const float* Eb = g_Epad + (size_t)b * SR * EE;
    if (tid < EE) { e0[tid] = Eb[2 * EE + tid]; eL[tid] = Eb[513 * EE + tid]; }
    __syncthreads();
    for (int kk = wid * 64; kk < wid * 64 + 64; ++kk) {
        float s0 = 0.f, sL = 0.f;
#pragma unroll
        for (int j = 0; j < 8; ++j) {
            int e = lane + j * 32;
            s0 += e0[e] * g_C0w[(size_t)kk * EE + e];
            sL += eL[e] * g_CLw[(size_t)kk * EE + e];
        }
#pragma unroll
        for (int o = 16; o; o >>= 1) {
            s0 += __shfl_xor_sync(0xFFFFFFFFu, s0, o);
            sL += __shfl_xor_sync(0xFFFFFFFFu, sL, o);
        }
        if (lane == 0) {
            g_corr0[(size_t)b * KK + kk] = s0;
            g_corrL[(size_t)b * KK + kk] = sL;
        }
    }
}

// ---------------- entity span features ----------------
__global__ void entity_kernel(const int* __restrict__ sidx,
                              const int* __restrict__ oidx) {
    const int b = blockIdx.x, e = threadIdx.x;     // 256
    const float* Eb = g_Epad + (size_t)b * SR * EE;
    for (int ent = 0; ent < 2; ++ent) {
        const int* ix = ent ? oidx : sidx;
        int s = ix[b * 2 + 0], en = ix[b * 2 + 1];
        int lo = s < 0 ? 0 : s;
        int hi = en > LL - 1 ? LL - 1 : en;
        float sum = 0.f; int cnt = 0;
        for (int l = lo; l <= hi; ++l) { sum += Eb[(size_t)(l + 2) * EE + e]; ++cnt; }
        float mean = sum / (float)cnt;
        int li = s - 1; if (li < 0) li += LL;
        float left = Eb[(size_t)(li + 2) * EE + e];
        float right = 0.f;
        if (en + 1 < LL) {
            int ri = en + 1; if (ri < 0) ri = 0;
            right = Eb[(size_t)(ri + 2) * EE + e];
        }
        float* dst = g_com + (size_t)b * 2048 + ent * 768;
        dst[e] = mean; dst[256 + e] = left; dst[512 + e] = right;
    }
}

// ---------------- wmma tf32 conv + fused max-pool ----------------
__device__ __forceinline__ void stage_chunk(int c, int l0, float* bufA, float* bufB,
                                            const float* Eb, const float* Pb,
                                            int k0, int tid) {
    const float* as; const float* bs; int astr, bstr;
    if (c < 40) {
        int d = c >> 3, ec = c & 7;
        as = Eb + (size_t)(l0 + d) * EE + ec * 32;               astr = EE;
        bs = g_Weff2 + ((size_t)d * KK + k0) * EE + ec * 32;     bstr = EE;
    } else {
        int cc = c - 40, t = cc >> 2, pc = cc & 3;
        as = Pb + (size_t)(l0 + t) * PR + pc * 32;               astr = PR;
        bs = g_Wp2 + ((size_t)t * KK + k0) * PR + pc * 32;       bstr = PR;
    }
    uint32_t dA = smem_u32(bufA), dB = smem_u32(bufB);
#pragma unroll
    for (int i = 0; i < 4; ++i) {
        int id = tid + i * 256;
        int r = id >> 3, c4 = id & 7;
        cpa16(dA + (uint32_t)(r * ALD + c4 * 4) * 4, as + (size_t)r * astr + c4 * 4);
        cpa16(dB + (uint32_t)(r * ALD + c4 * 4) * 4, bs + (size_t)r * bstr + c4 * 4);
    }
}

__global__ void __launch_bounds__(256, 2) conv_wmma_kernel(const float* __restrict__ conv_b) {
    extern __shared__ float smf[];
    const int tid = threadIdx.x, wid = tid >> 5;
    const int b = blockIdx.y, k0 = blockIdx.x * 128;
    const int lw = wid >> 2;        // 0..1 : l group (64 rows)
    const int kw = wid & 3;         // 0..3 : k group (32 cols)
    const float* Eb = g_Epad + (size_t)b * SR * EE;
    const float* Pb = g_Ppad + (size_t)b * SR * PR;

    float* bufA[2] = { smf,                smf + STAGE_FLOATS };
    float* bufB[2] = { smf + 128 * ALD,    smf + STAGE_FLOATS + 128 * ALD };

    float corr0v = 0.f, corrLv = 0.f, kmax = -3.4e38f;
    if (tid < 128) {
        corr0v = g_corr0[(size_t)b * KK + k0 + tid];
        corrLv = g_corrL[(size_t)b * KK + k0 + tid];
    }

    for (int l0 = 0; l0 < LL; l0 += 128) {
        wmma::fragment<wmma::accumulator, 16, 16, 8, float> acc[4][2];
#pragma unroll
        for (int mt = 0; mt < 4; ++mt)
#pragma unroll
            for (int nt = 0; nt < 2; ++nt)
                wmma::fill_fragment(acc[mt][nt], 0.f);

        stage_chunk(0, l0, bufA[0], bufB[0], Eb, Pb, k0, tid); CP_COMMIT();
        stage_chunk(1, l0, bufA[1], bufB[1], Eb, Pb, k0, tid); CP_COMMIT();

        for (int c = 0; c < CH; ++c) {
            if (c + 1 < CH) { CP_WAIT(1); } else { CP_WAIT(0); }
            __syncthreads();
            const float* A = bufA[c & 1];
            const float* Bm = bufB[c & 1];
#pragma unroll
            for (int ks = 0; ks < 4; ++ks) {
                wmma::fragment<wmma::matrix_b, 16, 16, 8, wmma::precision::tf32,
                               wmma::col_major> bf[2];
#pragma unroll
                for (int nt = 0; nt < 2; ++nt) {
                    wmma::load_matrix_sync(bf[nt], Bm + (kw * 32 + nt * 16) * ALD + ks * 8, ALD);
#pragma unroll
                    for (int t = 0; t < bf[nt].num_elements; ++t)
                        bf[nt].x[t] = wmma::__float_to_tf32(bf[nt].x[t]);
                }
#pragma unroll
                for (int mt = 0; mt < 4; ++mt) {
                    wmma::fragment<wmma::matrix_a, 16, 16, 8, wmma::precision::tf32,
                                   wmma::row_major> af;
                    wmma::load_matrix_sync(af, A + (lw * 64 + mt * 16) * ALD + ks * 8, ALD);
#pragma unroll
                    for (int t = 0; t < af.num_elements; ++t)
                        af.x[t] = wmma::__float_to_tf32(af.x[t]);
                    wmma::mma_sync(acc[mt][0], af, bf[0], acc[mt][0]);
                    wmma::mma_sync(acc[mt][1], af, bf[1], acc[mt][1]);
                }
            }
            __syncthreads();
            if (c + 2 < CH) {
                stage_chunk(c + 2, l0, bufA[c & 1], bufB[c & 1], Eb, Pb, k0, tid);
                CP_COMMIT();
            }
        }

        // epilogue for this l0 tile: C[128 l][128 k] -> smem (reuses stage union)
#pragma unroll
        for (int mt = 0; mt < 4; ++mt)
#pragma unroll
            for (int nt = 0; nt < 2; ++nt)
                wmma::store_matrix_sync(smf + (size_t)(lw * 64 + mt * 16) * 132
                                            + kw * 32 + nt * 16,
                                        acc[mt][nt], 132, wmma::mem_row_major);
        __syncthreads();
        if (tid < 128) {
            float m = -3.4e38f;
            for (int r = 0; r < 128; ++r) {
                float v = smf[(size_t)r * 132 + tid];
                if (l0 == 0 && r == 0)     v -= corr0v;
                if (l0 == 384 && r == 127) v -= corrLv;
                m = fmaxf(m, v);
            }
            kmax = fmaxf(kmax, m);
        }
        __syncthreads();
    }
    if (tid < 128)
        g_pooled[(size_t)b * KK + k0 + tid] = kmax + conv_b[k0 + tid];
}

// ---------------- sent_h = tanh(pooled @ lin1_w^T + b) ----------------
__global__ void lin1_kernel(const float* __restrict__ w, const float* __restrict__ bias) {
    const int b = blockIdx.x, h = threadIdx.x;     // 512
    __shared__ float p[KK];
    p[h] = g_pooled[(size_t)b * KK + h];
    __syncthreads();
    const float* wr = w + (size_t)h * KK;
    float s = bias[h];
#pragma unroll 8
    for (int i = 0; i < KK; ++i) s += p[i] * wr[i];
    g_com[(size_t)b * 2048 + 1536 + h] = tanhf(s);
}

// ---------------- scores = com @ lin2_w^T + b ----------------
__global__ void scores_kernel(const float* __restrict__ w, const float* __restrict__ bias,
                              float* __restrict__ out) {
    const int b = blockIdx.x, t = threadIdx.x;     // 64
    __shared__ float c[2048];
    for (int i = t; i < 2048; i += 64) c[i] = g_com[(size_t)b * 2048 + i];
    __syncthreads();
    if (t < TT) {
        const float* wr = w + (size_t)t * 2048;
        float s = bias[t];
#pragma unroll 8
        for (int i = 0; i < 2048; ++i) s += c[i] * wr[i];
        out[(size_t)b * TT + t] = s;
    }
}

// ---------------- launch ----------------
extern "C" void kernel_launch(void* const* d_in, const int* in_sizes, int n_in,
                              void* d_out, int out_size) {
    const int*   context = (const int*)  d_in[0];
    const int*   sidx    = (const int*)  d_in[1];
    const int*   oidx    = (const int*)  d_in[2];
    const int*   sdis    = (const int*)  d_in[3];
    const int*   odis    = (const int*)  d_in[4];
    const float* etab    = (const float*)d_in[5];
    const float* ptab    = (const float*)d_in[6];
    const float* conv_w  = (const float*)d_in[7];
    const float* conv_b  = (const float*)d_in[8];
    const float* lin1_w  = (const float*)d_in[9];
    const float* lin1_b  = (const float*)d_in[10];
    const float* lin2_w  = (const float*)d_in[11];
    const float* lin2_b  = (const float*)d_in[12];
    float* out = (float*)d_out;

    cudaFuncSetAttribute(conv_wmma_kernel,
                         cudaFuncAttributeMaxDynamicSharedMemorySize, SMEM_BYTES);

    zero_halo_kernel<<<BB, 256>>>();
    wprep_kernel<<<4352, 256>>>(conv_w);
    gather_kernel<<<dim3(16, BB), 256>>>(context, sdis, odis, etab, ptab);
    corr_kernel<<<BB, 256>>>(context);
    entity_kernel<<<BB, 256>>>(sidx, oidx);
    conv_wmma_kernel<<<dim3(4, BB), 256, SMEM_BYTES>>>(conv_b);
    lin1_kernel<<<BB, 512>>>(lin1_w, lin1_b);
    scores_kernel<<<BB, 64>>>(lin2_w, lin2_b, out);
}

// round 5
// speedup vs baseline: 4.6056x; 3.1926x over previous
#include <cuda_runtime.h>
#include <cuda_fp16.h>
#include <math.h>
#include <stdint.h>

#define BB   64
#define LL   512
#define EE   256
#define PR   128          // pos feature width (2*P)
#define KK   512
#define TT   53
#define SR   516          // padded rows (2-halo)
#define NCH  26           // K-chunks of 64 per l0 tile (20 embed + 6 pos)
#define NGI  (4 * NCH)    // flattened chunk count (4 l0 tiles)
#define STAGE_B 32768     // A(16KB) + B(16KB) per stage
#define SMEM_BYTES (3 * STAGE_B + 1024)

// ---------------- static device scratch ----------------
__device__ __align__(16) __half g_Eh[BB * SR * EE];    // [b][l+2][e] fp16
__device__ __align__(16) __half g_Ph[BB * SR * PR];    // [b][l+1][p] fp16
__device__ __align__(16) __half g_Wh[5 * KK * EE];     // [d][k][e] fp16
__device__ __align__(16) __half g_Wph[3 * KK * PR];    // [t][k][p] fp16
__device__ __align__(16) float  g_C0wT[EE * KK];       // [e][k] fp32
__device__ __align__(16) float  g_CLwT[EE * KK];       // [e][k] fp32
__device__ __align__(16) float  g_corr0[BB * KK];
__device__ __align__(16) float  g_corrL[BB * KK];
__device__ __align__(16) float  g_pooled[BB * KK];
__device__ __align__(16) float  g_com[BB * 2048];      // subj(768) obj(768) sent_h(512)

// ---------------- helpers ----------------
__device__ __forceinline__ uint32_t smem_u32(const void* p) {
    uint32_t a;
    asm("{ .reg .u64 t; cvta.to.shared.u64 t, %1; cvt.u32.u64 %0, t; }" : "=r"(a) : "l"(p));
    return a;
}
#define SWZ(off) ((off) ^ (((off) >> 3) & 0x70))
__device__ __forceinline__ void cpa16(uint32_t dst, const void* src) {
    asm volatile("cp.async.cg.shared.global [%0], [%1], 16;" :: "r"(dst), "l"(src) : "memory");
}
#define CP_COMMIT() asm volatile("cp.async.commit_group;" ::: "memory")
#define CP_WAIT(n)  asm volatile("cp.async.wait_group %0;" :: "n"(n) : "memory")
__device__ __forceinline__ void ldsm4(uint32_t* r, uint32_t addr) {
    asm volatile("ldmatrix.sync.aligned.m8n8.x4.shared.b16 {%0,%1,%2,%3}, [%4];"
                 : "=r"(r[0]), "=r"(r[1]), "=r"(r[2]), "=r"(r[3]) : "r"(addr));
}
__device__ __forceinline__ void mma16816(float* c, const uint32_t* a, uint32_t b0, uint32_t b1) {
    asm volatile("mma.sync.aligned.m16n8k16.row.col.f32.f16.f16.f32 "
                 "{%0,%1,%2,%3}, {%4,%5,%6,%7}, {%8,%9}, {%0,%1,%2,%3};"
                 : "+f"(c[0]), "+f"(c[1]), "+f"(c[2]), "+f"(c[3])
                 : "r"(a[0]), "r"(a[1]), "r"(a[2]), "r"(a[3]), "r"(b0), "r"(b1));
}

// ---------------- weight prep: fold + transpose + fp16 round ----------------
__global__ void wprep_kernel(const float* __restrict__ conv_w) {
    int idx = blockIdx.x * 256 + threadIdx.x;
    const int N1 = 5 * KK * EE;
    const int N2 = 3 * KK * PR;
    const int N3 = EE * KK;
    if (idx < N1) {
        int d = idx / (KK * EE), r = idx % (KK * EE);
        int k = r / EE, e = r % EE;
        float s = 0.f;
#pragma unroll
        for (int j = 0; j < 3; ++j) {
            int t = d - j;
            if (t >= 0 && t < 3)
                s += conv_w[((size_t)k * 896 + j * EE + e) * 3 + t];
        }
        g_Wh[idx] = __float2half(s);
    } else if (idx < N1 + N2) {
        int i2 = idx - N1;
        int t = i2 / (KK * PR), r = i2 % (KK * PR);
        int k = r / PR, p = r % PR;
        g_Wph[i2] = __float2half(conv_w[((size_t)k * 896 + 3 * EE + p) * 3 + t]);
    } else if (idx < N1 + N2 + N3) {
        int i3 = idx - N1 - N2;
        int e = i3 / KK, k = i3 % KK;
        g_C0wT[i3] = conv_w[((size_t)k * 896 + 2 * EE + e) * 3 + 0];
    } else if (idx < N1 + N2 + 2 * N3) {
        int i4 = idx - N1 - N2 - N3;
        int e = i4 / KK, k = i4 % KK;
        g_CLwT[i4] = conv_w[((size_t)k * 896 + e) * 3 + 2];
    }
}

// ---------------- gather (fp16, [l][e]) + halo zeroing ----------------
__global__ void gather_kernel(const int* __restrict__ context,
                              const int* __restrict__ sdis,
                              const int* __restrict__ odis,
                              const float* __restrict__ etab,
                              const float* __restrict__ ptab) {
    const int b = blockIdx.y;
    const int grp = threadIdx.x >> 5, lane = threadIdx.x & 31;
    __half* Eb = g_Eh + (size_t)b * SR * EE;
    __half* Pb = g_Ph + (size_t)b * SR * PR;
#pragma unroll
    for (int li = 0; li < 4; ++li) {
        int l = blockIdx.x * 32 + grp * 4 + li;
        int row = b * LL + l;
        int tok = context[row];
        const float* es = etab + (size_t)tok * EE;
        __half2* Erow = (__half2*)(Eb + (size_t)(l + 2) * EE);
#pragma unroll
        for (int it = 0; it < 4; ++it) {
            int i2 = it * 32 + lane;
            Erow[i2] = __floats2half2_rn(es[2 * i2], es[2 * i2 + 1]);
        }
        int ds = sdis[row], od = odis[row];
        __half2* Prow = (__half2*)(Pb + (size_t)(l + 1) * PR);
#pragma unroll
        for (int it = 0; it < 2; ++it) {
            int i2 = it * 32 + lane;
            int p = 2 * i2;
            float v0 = (p < 64) ? ptab[(size_t)ds * 64 + p] : ptab[(size_t)od * 64 + (p - 64)];
            float v1 = (p + 1 < 64) ? ptab[(size_t)ds * 64 + p + 1]
                                    : ptab[(size_t)od * 64 + (p + 1 - 64)];
            Prow[i2] = __floats2half2_rn(v0, v1);
        }
    }
    if (blockIdx.x == 0) {
        const int t = threadIdx.x;
        const __half2 z = __floats2half2_rn(0.f, 0.f);
        const int erows[4] = {0, 1, 514, 515};
        const int prows[4] = {0, 513, 514, 515};
#pragma unroll
        for (int i = 0; i < 2; ++i) {
            int idx = t + i * 256;                 // 0..511
            ((__half2*)Eb)[(size_t)erows[idx >> 7] * 128 + (idx & 127)] = z;
        }
        ((__half2*)Pb)[(size_t)prows[t >> 6] * 64 + (t & 63)] = z;
    }
}

// ---------------- entity features + boundary corrections (fused) ----------------
__global__ void entcorr_kernel(const int* __restrict__ sidx,
                               const int* __restrict__ oidx) {
    const int b = blockIdx.x, tid = threadIdx.x;   // 512
    __shared__ float e0[EE], eL[EE];
    const __half* Eb = g_Eh + (size_t)b * SR * EE;
    if (tid < EE) {
        e0[tid] = __half2float(Eb[2 * EE + tid]);
        eL[tid] = __half2float(Eb[513 * EE + tid]);
    }
    __syncthreads();
    {   // corrections: thread k = tid, coalesced over [e][k]
        float s0 = 0.f, sL = 0.f;
#pragma unroll 4
        for (int e = 0; e < EE; ++e) {
            s0 += e0[e] * g_C0wT[(size_t)e * KK + tid];
            sL += eL[e] * g_CLwT[(size_t)e * KK + tid];
        }
        g_corr0[(size_t)b * KK + tid] = s0;
        g_corrL[(size_t)b * KK + tid] = sL;
    }
    if (tid < EE) {
        const int e = tid;
        for (int ent = 0; ent < 2; ++ent) {
            const int* ix = ent ? oidx : sidx;
            int s = ix[b * 2 + 0], en = ix[b * 2 + 1];
            int lo = s < 0 ? 0 : s;
            int hi = en > LL - 1 ? LL - 1 : en;
            float sum = 0.f; int cnt = 0;
            for (int l = lo; l <= hi; ++l) {
                sum += __half2float(Eb[(size_t)(l + 2) * EE + e]); ++cnt;
            }
            float mean = sum / (float)cnt;
            int li = s - 1; if (li < 0) li += LL;
            float left = __half2float(Eb[(size_t)(li + 2) * EE + e]);
            float right = 0.f;
            if (en + 1 < LL) {
                int ri = en + 1; if (ri < 0) ri = 0;
                right = __half2float(Eb[(size_t)(ri + 2) * EE + e]);
            }
            float* dst = g_com + (size_t)b * 2048 + ent * 768;
            dst[e] = mean; dst[256 + e] = left; dst[512 + e] = right;
        }
    }
}

// ---------------- fp16 mma conv + fused max-pool ----------------
__device__ __forceinline__ void stage_chunk(int gi, uint32_t sbase,
                                            const __half* Eb, const __half* Pb,
                                            int k0, int tid) {
    int l0 = (gi / NCH) * 128;
    int c  = gi - (gi / NCH) * NCH;
    const __half* as; const __half* bs; int astr, bstr;
    if (c < 20) {
        int d = c >> 2, ec = c & 3;
        as = Eb + (size_t)(l0 + d) * EE + ec * 64;               astr = EE;
        bs = g_Wh + ((size_t)d * KK + k0) * EE + ec * 64;        bstr = EE;
    } else {
        int cc = c - 20, t = cc >> 1, pc = cc & 1;
        as = Pb + (size_t)(l0 + t) * PR + pc * 64;               astr = PR;
        bs = g_Wph + ((size_t)t * KK + k0) * PR + pc * 64;       bstr = PR;
    }
    const uint32_t st = sbase + (uint32_t)(gi % 3) * STAGE_B;
#pragma unroll
    for (int i = 0; i < 4; ++i) {
        int id = tid + i * 256;
        int r = id >> 3, c16 = id & 7;
        uint32_t off = SWZ((uint32_t)(r * 128 + c16 * 16));
        cpa16(st + off,         (const char*)(as + (size_t)r * astr) + c16 * 16);
        cpa16(st + 16384 + off, (const char*)(bs + (size_t)r * bstr) + c16 * 16);
    }
}

__global__ void __launch_bounds__(256, 2) conv_mma_kernel(const float* __restrict__ conv_b) {
    extern __shared__ char smem[];
    const uint32_t sbase = smem_u32(smem);
    float* red = (float*)(smem + 3 * STAGE_B);
    const int tid = threadIdx.x, wid = tid >> 5, lane = tid & 31;
    const int lw = wid >> 2;          // 0..1 : 64 l-rows
    const int kw = wid & 3;           // 0..3 : 32 k-cols
    const int b = blockIdx.y, k0 = blockIdx.x * 128;
    const __half* Eb = g_Eh + (size_t)b * SR * EE;
    const __half* Pb = g_Ph + (size_t)b * SR * PR;

    const int rquad = lane >> 2, rlo = lane & 3;
    const int rowA = lw * 64 + (lane & 7) + ((lane >> 3) & 1) * 8;
    const int rowB = kw * 32 + (lane & 7) + ((lane >> 3) & 1) * 8;
    const int kbl  = (lane >> 4) * 16;

    float acc[4][4][4];
    float colmax[4][2];
#pragma unroll
    for (int nt = 0; nt < 4; ++nt) { colmax[nt][0] = -3.4e38f; colmax[nt][1] = -3.4e38f; }

    stage_chunk(0, sbase, Eb, Pb, k0, tid); CP_COMMIT();
    stage_chunk(1, sbase, Eb, Pb, k0, tid); CP_COMMIT();

    for (int gi = 0; gi < NGI; ++gi) {
        if (gi == NGI - 1) { CP_WAIT(0); } else { CP_WAIT(1); }
        __syncthreads();
        if (gi % NCH == 0) {
#pragma unroll
            for (int mt = 0; mt < 4; ++mt)
#pragma unroll
                for (int nt = 0; nt < 4; ++nt)
#pragma unroll
                    for (int j = 0; j < 4; ++j) acc[mt][nt][j] = 0.f;
        }
        const uint32_t sA = sbase + (uint32_t)(gi % 3) * STAGE_B;
        const uint32_t sB = sA + 16384;
#pragma unroll
        for (int ks = 0; ks < 4; ++ks) {
            uint32_t a[4][4], bf[2][4];
#pragma unroll
            for (int mt = 0; mt < 4; ++mt)
                ldsm4(a[mt], sA + SWZ((uint32_t)((rowA + mt * 16) * 128 + ks * 32 + kbl)));
#pragma unroll
            for (int bt = 0; bt < 2; ++bt)
                ldsm4(bf[bt], sB + SWZ((uint32_t)((rowB + bt * 16) * 128 + ks * 32 + kbl)));
#pragma unroll
            for (int mt = 0; mt < 4; ++mt) {
                mma16816(acc[mt][0], a[mt], bf[0][0], bf[0][2]);
                mma16816(acc[mt][1], a[mt], bf[0][1], bf[0][3]);
                mma16816(acc[mt][2], a[mt], bf[1][0], bf[1][2]);
                mma16816(acc[mt][3], a[mt], bf[1][1], bf[1][3]);
            }
        }
        if (gi + 2 < NGI) { stage_chunk(gi + 2, sbase, Eb, Pb, k0, tid); CP_COMMIT(); }
        if (gi % NCH == NCH - 1) {
            const int l0 = (gi / NCH) * 128;
            if (l0 == 0 && lw == 0 && rquad == 0) {        // global row 0
#pragma unroll
                for (int nt = 0; nt < 4; ++nt) {
                    int n = k0 + kw * 32 + nt * 8 + rlo * 2;
                    acc[0][nt][0] -= g_corr0[(size_t)b * KK + n];
                    acc[0][nt][1] -= g_corr0[(size_t)b * KK + n + 1];
                }
            }
            if (l0 == 384 && lw == 1 && rquad == 7) {      // global row 511
#pragma unroll
                for (int nt = 0; nt < 4; ++nt) {
                    int n = k0 + kw * 32 + nt * 8 + rlo * 2;
                    acc[3][nt][2] -= g_corrL[(size_t)b * KK + n];
                    acc[3][nt][3] -= g_corrL[(size_t)b * KK + n + 1];
                }
            }
#pragma unroll
            for (int mt = 0; mt < 4; ++mt)
#pragma unroll
                for (int nt = 0; nt < 4; ++nt) {
                    colmax[nt][0] = fmaxf(colmax[nt][0], fmaxf(acc[mt][nt][0], acc[mt][nt][2]));
                    colmax[nt][1] = fmaxf(colmax[nt][1], fmaxf(acc[mt][nt][1], acc[mt][nt][3]));
                }
        }
    }
    // reduce over 8 row-quads (lanes sharing lane&3) then across lw groups
#pragma unroll
    for (int nt = 0; nt < 4; ++nt)
#pragma unroll
        for (int j = 0; j < 2; ++j) {
            float v = colmax[nt][j];
            v = fmaxf(v, __shfl_xor_sync(0xFFFFFFFFu, v, 4));
            v = fmaxf(v, __shfl_xor_sync(0xFFFFFFFFu, v, 8));
            v = fmaxf(v, __shfl_xor_sync(0xFFFFFFFFu, v, 16));
            if (rquad == 0)
                red[lw * 128 + kw * 32 + nt * 8 + rlo * 2 + j] = v;
        }
    __syncthreads();
    if (tid < 128)
        g_pooled[(size_t)b * KK + k0 + tid] =
            fmaxf(red[tid], red[128 + tid]) + conv_b[k0 + tid];
}

// ---------------- lin1 (tanh) + scores (fused) ----------------
__global__ void lin12_kernel(const float* __restrict__ w1, const float* __restrict__ b1,
                             const float* __restrict__ w2, const float* __restrict__ b2,
                             float* __restrict__ out) {
    const int b = blockIdx.x, tid = threadIdx.x;   // 512
    __shared__ float p[KK];
    __shared__ float c[2048];
    p[tid] = g_pooled[(size_t)b * KK + tid];
#pragma unroll
    for (int i = 0; i < 3; ++i)
        c[tid + i * 512] = g_com[(size_t)b * 2048 + tid + i * 512];
    __syncthreads();
    {
        const float* wr = w1 + (size_t)tid * KK;
        float s = b1[tid];
#pragma unroll 8
        for (int i = 0; i < KK; ++i) s += p[i] * wr[i];
        c[1536 + tid] = tanhf(s);
    }
    __syncthreads();
    const int w = tid >> 5, ln = tid & 31;
    for (int t = w; t < TT; t += 16) {
        const float* wr = w2 + (size_t)t * 2048;
        float s = 0.f;
#pragma unroll 8
        for (int i = ln; i < 2048; i += 32) s += c[i] * wr[i];
#pragma unroll
        for (int o = 16; o; o >>= 1) s += __shfl_xor_sync(0xFFFFFFFFu, s, o);
        if (ln == 0) out[(size_t)b * TT + t] = s + b2[t];
    }
}

// ---------------- launch ----------------
extern "C" void kernel_launch(void* const* d_in, const int* in_sizes, int n_in,
                              void* d_out, int out_size) {
    const int*   context = (const int*)  d_in[0];
    const int*   sidx    = (const int*)  d_in[1];
    const int*   oidx    = (const int*)  d_in[2];
    const int*   sdis    = (const int*)  d_in[3];
    const int*   odis    = (const int*)  d_in[4];
    const float* etab    = (const float*)d_in[5];
    const float* ptab    = (const float*)d_in[6];
    const float* conv_w  = (const float*)d_in[7];
    const float* conv_b  = (const float*)d_in[8];
    const float* lin1_w  = (const float*)d_in[9];
    const float* lin1_b  = (const float*)d_in[10];
    const float* lin2_w  = (const float*)d_in[11];
    const float* lin2_b  = (const float*)d_in[12];
    float* out = (float*)d_out;

    cudaFuncSetAttribute(conv_mma_kernel,
                         cudaFuncAttributeMaxDynamicSharedMemorySize, SMEM_BYTES);

    wprep_kernel<<<4352, 256>>>(conv_w);
    gather_kernel<<<dim3(16, BB), 256>>>(context, sdis, odis, etab, ptab);
    entcorr_kernel<<<BB, 512>>>(sidx, oidx);
    conv_mma_kernel<<<dim3(4, BB), 256, SMEM_BYTES>>>(conv_b);
    lin12_kernel<<<BB, 512>>>(lin1_w, lin1_b, lin2_w, lin2_b, out);
}

// round 6
// speedup vs baseline: 6.2001x; 1.3462x over previous
#include <cuda_runtime.h>
#include <cuda_fp16.h>
#include <math.h>
#include <stdint.h>

#define BB   64
#define LL   512
#define EE   256
#define PR   128          // pos feature width (2*P)
#define KK   512
#define TT   53
#define SR   516          // padded rows (2-halo)
#define NCH  26           // K-chunks of 64 per l0 tile (20 embed + 6 pos)
#define NGI  (4 * NCH)    // flattened chunk count (4 l0 tiles)
#define STAGE_B 32768     // A(16KB) + B(16KB) per stage
#define SMEM_BYTES (3 * STAGE_B + 1024)

// ---------------- static device scratch ----------------
__device__ __align__(16) __half g_Eh[BB * SR * EE];    // [b][l+2][e] fp16
__device__ __align__(16) __half g_Ph[BB * SR * PR];    // [b][l+1][p] fp16
__device__ __align__(16) __half g_Wh[5 * KK * EE];     // [d][k][e] fp16
__device__ __align__(16) __half g_Wph[3 * KK * PR];    // [t][k][p] fp16
__device__ __align__(16) float  g_C0w[KK * EE];        // [k][e] fp32
__device__ __align__(16) float  g_CLw[KK * EE];        // [k][e] fp32
__device__ __align__(16) float  g_corr0[BB * KK];
__device__ __align__(16) float  g_corrL[BB * KK];
__device__ __align__(16) float  g_pooled[BB * KK];
__device__ __align__(16) float  g_com[BB * 2048];      // subj(768) obj(768) sent_h(512)

// ---------------- helpers ----------------
__device__ __forceinline__ uint32_t smem_u32(const void* p) {
    uint32_t a;
    asm("{ .reg .u64 t; cvta.to.shared.u64 t, %1; cvt.u32.u64 %0, t; }" : "=r"(a) : "l"(p));
    return a;
}
#define SWZ(off) ((off) ^ (((off) >> 3) & 0x70))
__device__ __forceinline__ void cpa16(uint32_t dst, const void* src) {
    asm volatile("cp.async.cg.shared.global [%0], [%1], 16;" :: "r"(dst), "l"(src) : "memory");
}
#define CP_COMMIT() asm volatile("cp.async.commit_group;" ::: "memory")
#define CP_WAIT(n)  asm volatile("cp.async.wait_group %0;" :: "n"(n) : "memory")
__device__ __forceinline__ void ldsm4(uint32_t* r, uint32_t addr) {
    asm volatile("ldmatrix.sync.aligned.m8n8.x4.shared.b16 {%0,%1,%2,%3}, [%4];"
                 : "=r"(r[0]), "=r"(r[1]), "=r"(r[2]), "=r"(r[3]) : "r"(addr));
}
__device__ __forceinline__ void mma16816(float* c, const uint32_t* a, uint32_t b0, uint32_t b1) {
    asm volatile("mma.sync.aligned.m16n8k16.row.col.f32.f16.f16.f32 "
                 "{%0,%1,%2,%3}, {%4,%5,%6,%7}, {%8,%9}, {%0,%1,%2,%3};"
                 : "+f"(c[0]), "+f"(c[1]), "+f"(c[2]), "+f"(c[3])
                 : "r"(a[0]), "r"(a[1]), "r"(a[2]), "r"(a[3]), "r"(b0), "r"(b1));
}

// ---------------- weight prep: one block per k, smem-staged, all coalesced ----------------
__global__ void wprep_kernel(const float* __restrict__ conv_w) {
    const int k = blockIdx.x;            // 512 blocks
    const int tid = threadIdx.x;         // 256
    __shared__ float w[2688];            // conv_w row: [j*256+e or 768+p][3]
    const float* src = conv_w + (size_t)k * 2688;
    for (int i = tid; i < 2688; i += 256) w[i] = src[i];
    __syncthreads();
    const int e = tid;
#pragma unroll
    for (int d = 0; d < 5; ++d) {
        float s = 0.f;
#pragma unroll
        for (int j = 0; j < 3; ++j) {
            int t = d - j;
            if (t >= 0 && t < 3) s += w[(j * EE + e) * 3 + t];
        }
        g_Wh[((size_t)d * KK + k) * EE + e] = __float2half(s);
    }
    if (tid < PR) {
#pragma unroll
        for (int t = 0; t < 3; ++t)
            g_Wph[((size_t)t * KK + k) * PR + tid] = __float2half(w[(768 + tid) * 3 + t]);
    }
    g_C0w[(size_t)k * EE + e] = w[(2 * EE + e) * 3 + 0];
    g_CLw[(size_t)k * EE + e] = w[e * 3 + 2];
}

// ---------------- gather (fp16, [l][e]) + halo zeroing, vectorized ----------------
__global__ void gather_kernel(const int* __restrict__ context,
                              const int* __restrict__ sdis,
                              const int* __restrict__ odis,
                              const float* __restrict__ etab,
                              const float* __restrict__ ptab) {
    const int b = blockIdx.y;
    const int grp = threadIdx.x >> 5, lane = threadIdx.x & 31;
    __half* Eb = g_Eh + (size_t)b * SR * EE;
    __half* Pb = g_Ph + (size_t)b * SR * PR;
#pragma unroll
    for (int li = 0; li < 4; ++li) {
        int l = blockIdx.x * 32 + grp * 4 + li;
        int row = b * LL + l;
        int tok = context[row];
        const float4* es4 = (const float4*)(etab + (size_t)tok * EE);
        uint2* Erow = (uint2*)(Eb + (size_t)(l + 2) * EE);   // 64 x (4 halfs)
#pragma unroll
        for (int it = 0; it < 2; ++it) {
            int j = it * 32 + lane;
            float4 f = es4[j];
            __half2 h01 = __floats2half2_rn(f.x, f.y);
            __half2 h23 = __floats2half2_rn(f.z, f.w);
            uint2 u;
            u.x = *(uint32_t*)&h01; u.y = *(uint32_t*)&h23;
            Erow[j] = u;
        }
        int ds = sdis[row], od = odis[row];
        uint2* Prow = (uint2*)(Pb + (size_t)(l + 1) * PR);   // 32 x (4 halfs)
        {
            int j = lane;
            float4 f = (j < 16) ? ((const float4*)(ptab + (size_t)ds * 64))[j]
                                : ((const float4*)(ptab + (size_t)od * 64))[j - 16];
            __half2 h01 = __floats2half2_rn(f.x, f.y);
            __half2 h23 = __floats2half2_rn(f.z, f.w);
            uint2 u;
            u.x = *(uint32_t*)&h01; u.y = *(uint32_t*)&h23;
            Prow[j] = u;
        }
    }
    if (blockIdx.x == 0) {
        const int t = threadIdx.x;
        const __half2 z = __floats2half2_rn(0.f, 0.f);
        const int erows[4] = {0, 1, 514, 515};
        const int prows[4] = {0, 513, 514, 515};
#pragma unroll
        for (int i = 0; i < 2; ++i) {
            int idx = t + i * 256;
            ((__half2*)Eb)[(size_t)erows[idx >> 7] * 128 + (idx & 127)] = z;
        }
        ((__half2*)Pb)[(size_t)prows[t >> 6] * 64 + (t & 63)] = z;
    }
}

// ---------------- entity features + boundary corrections (fused) ----------------
__global__ void entcorr_kernel(const int* __restrict__ sidx,
                               const int* __restrict__ oidx) {
    const int b = blockIdx.x, tid = threadIdx.x;   // 512
    const int wid = tid >> 5, lane = tid & 31;
    __shared__ float e0[EE], eL[EE];
    const __half* Eb = g_Eh + (size_t)b * SR * EE;
    if (tid < EE) {
        e0[tid] = __half2float(Eb[2 * EE + tid]);
        eL[tid] = __half2float(Eb[513 * EE + tid]);
    }
    __syncthreads();
    // corrections: warp per k, coalesced reads of [k][e]
    for (int ko = 0; ko < 32; ++ko) {
        int k = wid * 32 + ko;
        float s0 = 0.f, sL = 0.f;
#pragma unroll
        for (int q = 0; q < 8; ++q) {
            int e = lane + q * 32;
            s0 += e0[e] * g_C0w[(size_t)k * EE + e];
            sL += eL[e] * g_CLw[(size_t)k * EE + e];
        }
#pragma unroll
        for (int o = 16; o; o >>= 1) {
            s0 += __shfl_xor_sync(0xFFFFFFFFu, s0, o);
            sL += __shfl_xor_sync(0xFFFFFFFFu, sL, o);
        }
        if (lane == 0) {
            g_corr0[(size_t)b * KK + k] = s0;
            g_corrL[(size_t)b * KK + k] = sL;
        }
    }
    if (tid < EE) {
        const int e = tid;
        for (int ent = 0; ent < 2; ++ent) {
            const int* ix = ent ? oidx : sidx;
            int s = ix[b * 2 + 0], en = ix[b * 2 + 1];
            int lo = s < 0 ? 0 : s;
            int hi = en > LL - 1 ? LL - 1 : en;
            float sum = 0.f; int cnt = 0;
            for (int l = lo; l <= hi; ++l) {
                sum += __half2float(Eb[(size_t)(l + 2) * EE + e]); ++cnt;
            }
            float mean = sum / (float)cnt;
            int li = s - 1; if (li < 0) li += LL;
            float left = __half2float(Eb[(size_t)(li + 2) * EE + e]);
            float right = 0.f;
            if (en + 1 < LL) {
                int ri = en + 1; if (ri < 0) ri = 0;
                right = __half2float(Eb[(size_t)(ri + 2) * EE + e]);
            }
            float* dst = g_com + (size_t)b * 2048 + ent * 768;
            dst[e] = mean; dst[256 + e] = left; dst[512 + e] = right;
        }
    }
}

// ---------------- fp16 mma conv + fused max-pool ----------------
__device__ __forceinline__ void stage_chunk(int gi, uint32_t sbase,
                                            const __half* Eb, const __half* Pb,
                                            int k0, int tid) {
    int l0 = (gi / NCH) * 128;
    int c  = gi - (gi / NCH) * NCH;
    const __half* as; const __half* bs; int astr, bstr;
    if (c < 20) {
        int d = c >> 2, ec = c & 3;
        as = Eb + (size_t)(l0 + d) * EE + ec * 64;               astr = EE;
        bs = g_Wh + ((size_t)d * KK + k0) * EE + ec * 64;        bstr = EE;
    } else {
        int cc = c - 20, t = cc >> 1, pc = cc & 1;
        as = Pb + (size_t)(l0 + t) * PR + pc * 64;               astr = PR;
        bs = g_Wph + ((size_t)t * KK + k0) * PR + pc * 64;       bstr = PR;
    }
    const uint32_t st = sbase + (uint32_t)(gi % 3) * STAGE_B;
#pragma unroll
    for (int i = 0; i < 4; ++i) {
        int id = tid + i * 256;
        int r = id >> 3, c16 = id & 7;
        uint32_t off = SWZ((uint32_t)(r * 128 + c16 * 16));
        cpa16(st + off,         (const char*)(as + (size_t)r * astr) + c16 * 16);
        cpa16(st + 16384 + off, (const char*)(bs + (size_t)r * bstr) + c16 * 16);
    }
}

__global__ void __launch_bounds__(256, 2) conv_mma_kernel(const float* __restrict__ conv_b) {
    extern __shared__ char smem[];
    const uint32_t sbase = smem_u32(smem);
    float* red = (float*)(smem + 3 * STAGE_B);
    const int tid = threadIdx.x, wid = tid >> 5, lane = tid & 31;
    const int lw = wid >> 2;          // 0..1 : 64 l-rows
    const int kw = wid & 3;           // 0..3 : 32 k-cols
    const int b = blockIdx.y, k0 = blockIdx.x * 128;
    const __half* Eb = g_Eh + (size_t)b * SR * EE;
    const __half* Pb = g_Ph + (size_t)b * SR * PR;

    const int rquad = lane >> 2, rlo = lane & 3;
    const int rowA = lw * 64 + (lane & 7) + ((lane >> 3) & 1) * 8;
    const int rowB = kw * 32 + (lane & 7) + ((lane >> 3) & 1) * 8;
    const int kbl  = (lane >> 4) * 16;

    float acc[4][4][4];
    float colmax[4][2];
#pragma unroll
    for (int nt = 0; nt < 4; ++nt) { colmax[nt][0] = -3.4e38f; colmax[nt][1] = -3.4e38f; }

    stage_chunk(0, sbase, Eb, Pb, k0, tid); CP_COMMIT();
    stage_chunk(1, sbase, Eb, Pb, k0, tid); CP_COMMIT();

    for (int gi = 0; gi < NGI; ++gi) {
        if (gi == NGI - 1) { CP_WAIT(0); } else { CP_WAIT(1); }
        __syncthreads();
        // prefetch FIRST so LDGSTS overlaps the whole MMA block below
        if (gi + 2 < NGI) { stage_chunk(gi + 2, sbase, Eb, Pb, k0, tid); CP_COMMIT(); }
        if (gi % NCH == 0) {
#pragma unroll
            for (int mt = 0; mt < 4; ++mt)
#pragma unroll
                for (int nt = 0; nt < 4; ++nt)
#pragma unroll
                    for (int j = 0; j < 4; ++j) acc[mt][nt][j] = 0.f;
        }
        const uint32_t sA = sbase + (uint32_t)(gi % 3) * STAGE_B;
        const uint32_t sB = sA + 16384;
#pragma unroll
        for (int ks = 0; ks < 4; ++ks) {
            uint32_t a[4][4], bf[2][4];
#pragma unroll
            for (int mt = 0; mt < 4; ++mt)
                ldsm4(a[mt], sA + SWZ((uint32_t)((rowA + mt * 16) * 128 + ks * 32 + kbl)));
#pragma unroll
            for (int bt = 0; bt < 2; ++bt)
                ldsm4(bf[bt], sB + SWZ((uint32_t)((rowB + bt * 16) * 128 + ks * 32 + kbl)));
#pragma unroll
            for (int mt = 0; mt < 4; ++mt) {
                mma16816(acc[mt][0], a[mt], bf[0][0], bf[0][2]);
                mma16816(acc[mt][1], a[mt], bf[0][1], bf[0][3]);
                mma16816(acc[mt][2], a[mt], bf[1][0], bf[1][2]);
                mma16816(acc[mt][3], a[mt], bf[1][1], bf[1][3]);
            }
        }
        if (gi % NCH == NCH - 1) {
            const int l0 = (gi / NCH) * 128;
            if (l0 == 0 && lw == 0 && rquad == 0) {        // global row 0
#pragma unroll
                for (int nt = 0; nt < 4; ++nt) {
                    int n = k0 + kw * 32 + nt * 8 + rlo * 2;
                    acc[0][nt][0] -= g_corr0[(size_t)b * KK + n];
                    acc[0][nt][1] -= g_corr0[(size_t)b * KK + n + 1];
                }
            }
            if (l0 == 384 && lw == 1 && rquad == 7) {      // global row 511
#pragma unroll
                for (int nt = 0; nt < 4; ++nt) {
                    int n = k0 + kw * 32 + nt * 8 + rlo * 2;
                    acc[3][nt][2] -= g_corrL[(size_t)b * KK + n];
                    acc[3][nt][3] -= g_corrL[(size_t)b * KK + n + 1];
                }
            }
#pragma unroll
            for (int mt = 0; mt < 4; ++mt)
#pragma unroll
                for (int nt = 0; nt < 4; ++nt) {
                    colmax[nt][0] = fmaxf(colmax[nt][0], fmaxf(acc[mt][nt][0], acc[mt][nt][2]));
                    colmax[nt][1] = fmaxf(colmax[nt][1], fmaxf(acc[mt][nt][1], acc[mt][nt][3]));
                }
        }
    }
    // reduce over 8 row-quads then across lw groups
#pragma unroll
    for (int nt = 0; nt < 4; ++nt)
#pragma unroll
        for (int j = 0; j < 2; ++j) {
            float v = colmax[nt][j];
            v = fmaxf(v, __shfl_xor_sync(0xFFFFFFFFu, v, 4));
            v = fmaxf(v, __shfl_xor_sync(0xFFFFFFFFu, v, 8));
            v = fmaxf(v, __shfl_xor_sync(0xFFFFFFFFu, v, 16));
            if (rquad == 0)
                red[lw * 128 + kw * 32 + nt * 8 + rlo * 2 + j] = v;
        }
    __syncthreads();
    if (tid < 128)
        g_pooled[(size_t)b * KK + k0 + tid] =
            fmaxf(red[tid], red[128 + tid]) + conv_b[k0 + tid];
}

// ---------------- lin1 (tanh) + scores, warp-per-row + float4 ----------------
__global__ void lin12_kernel(const float* __restrict__ w1, const float* __restrict__ b1,
                             const float* __restrict__ w2, const float* __restrict__ b2,
                             float* __restrict__ out) {
    const int b = blockIdx.x, tid = threadIdx.x;   // 512
    const int w = tid >> 5, lane = tid & 31;
    __shared__ float p[KK];
    __shared__ float c[2048];
    p[tid] = g_pooled[(size_t)b * KK + tid];
#pragma unroll
    for (int i = 0; i < 3; ++i)
        c[tid + i * 512] = g_com[(size_t)b * 2048 + tid + i * 512];
    __syncthreads();
    const float4* p4 = (const float4*)p;
    for (int hr = 0; hr < 32; ++hr) {
        int h = w * 32 + hr;
        const float4* wr4 = (const float4*)(w1 + (size_t)h * KK);
        float s = 0.f;
#pragma unroll
        for (int q = 0; q < 4; ++q) {
            int j = lane + q * 32;
            float4 f = wr4[j], g = p4[j];
            s += f.x * g.x + f.y * g.y + f.z * g.z + f.w * g.w;
        }
#pragma unroll
        for (int o = 16; o; o >>= 1) s += __shfl_xor_sync(0xFFFFFFFFu, s, o);
        if (lane == 0) c[1536 + h] = tanhf(s + b1[h]);
    }
    __syncthreads();
    const float4* c4 = (const float4*)c;
    for (int t = w; t < TT; t += 16) {
        const float4* wr4 = (const float4*)(w2 + (size_t)t * 2048);
        float s = 0.f;
#pragma unroll
        for (int q = 0; q < 16; ++q) {
            int j = lane + q * 32;
            float4 f = wr4[j], g = c4[j];
            s += f.x * g.x + f.y * g.y + f.z * g.z + f.w * g.w;
        }
#pragma unroll
        for (int o = 16; o; o >>= 1) s += __shfl_xor_sync(0xFFFFFFFFu, s, o);
        if (lane == 0) out[(size_t)b * TT + t] = s + b2[t];
    }
}

// ---------------- launch ----------------
extern "C" void kernel_launch(void* const* d_in, const int* in_sizes, int n_in,
                              void* d_out, int out_size) {
    const int*   context = (const int*)  d_in[0];
    const int*   sidx    = (const int*)  d_in[1];
    const int*   oidx    = (const int*)  d_in[2];
    const int*   sdis    = (const int*)  d_in[3];
    const int*   odis    = (const int*)  d_in[4];
    const float* etab    = (const float*)d_in[5];
    const float* ptab    = (const float*)d_in[6];
    const float* conv_w  = (const float*)d_in[7];
    const float* conv_b  = (const float*)d_in[8];
    const float* lin1_w  = (const float*)d_in[9];
    const float* lin1_b  = (const float*)d_in[10];
    const float* lin2_w  = (const float*)d_in[11];
    const float* lin2_b  = (const float*)d_in[12];
    float* out = (float*)d_out;

    cudaFuncSetAttribute(conv_mma_kernel,
                         cudaFuncAttributeMaxDynamicSharedMemorySize, SMEM_BYTES);

    wprep_kernel<<<KK, 256>>>(conv_w);
    gather_kernel<<<dim3(16, BB), 256>>>(context, sdis, odis, etab, ptab);
    entcorr_kernel<<<BB, 512>>>(sidx, oidx);
    conv_mma_kernel<<<dim3(4, BB), 256, SMEM_BYTES>>>(conv_b);
    lin12_kernel<<<BB, 512>>>(lin1_w, lin1_b, lin2_w, lin2_b, out);
}